// round 16
// baseline (speedup 1.0000x reference)
#include <cuda_runtime.h>
#include <cuda_fp16.h>
#include <math.h>
#include <stdint.h>

#define NTOK  16384
#define DIM   512
#define NEXP  8
#define BM    128
#define BN    128
#define BK    64
#define KSTAGES (DIM / BK)          // 8
#define GEMM_GRID 296               // 2 CTAs x 148 SMs
#define GTHREADS 128                // 4 warps, 2x2 grid of 64x64 warp tiles

// ---------------- static device scratch ------------------------------------
__device__ int     g_count[NEXP];
__device__ int     g_ticket;
__device__ int     g_done;
__device__ int     g_tok [NEXP][NTOK];
__device__ float   g_gate[NEXP][NTOK];
__device__ __half  g_x  [NTOK * DIM];
__device__ __half  g_wk [NEXP * DIM * DIM];         // [e][n][k] fp16

// ---------------- helpers ---------------------------------------------------
__device__ __forceinline__ uint32_t smem_u32(const void* p) {
    uint32_t a;
    asm("{ .reg .u64 t; cvta.to.shared.u64 t, %1; cvt.u32.u64 %0, t; }" : "=r"(a) : "l"(p));
    return a;
}
__device__ __forceinline__ void cp16(uint32_t saddr, const void* g) {
    asm volatile("cp.async.cg.shared.global [%0], [%1], 16;" :: "r"(saddr), "l"(g));
}
__device__ __forceinline__ void cp_commit() { asm volatile("cp.async.commit_group;"); }
template<int N> __device__ __forceinline__ void cp_wait() {
    asm volatile("cp.async.wait_group %0;" :: "n"(N));
}
__device__ __forceinline__ void ldsm4(uint32_t& r0, uint32_t& r1, uint32_t& r2, uint32_t& r3,
                                      uint32_t addr) {
    asm volatile("ldmatrix.sync.aligned.m8n8.x4.shared.b16 {%0,%1,%2,%3}, [%4];"
                 : "=r"(r0), "=r"(r1), "=r"(r2), "=r"(r3) : "r"(addr));
}
__device__ __forceinline__ void mma16816(float* c, const uint32_t* a, const uint32_t* b) {
    asm volatile(
        "mma.sync.aligned.m16n8k16.row.col.f32.f16.f16.f32 "
        "{%0,%1,%2,%3}, {%4,%5,%6,%7}, {%8,%9}, {%0,%1,%2,%3};"
        : "+f"(c[0]), "+f"(c[1]), "+f"(c[2]), "+f"(c[3])
        : "r"(a[0]), "r"(a[1]), "r"(a[2]), "r"(a[3]), "r"(b[0]), "r"(b[1]));
}
__device__ __forceinline__ void redf2(float* p, float a, float b) {
    asm volatile("red.global.add.v2.f32 [%0], {%1, %2};"
                 :: "l"(p), "f"(a), "f"(b) : "memory");
}

// ---------------- fused prep + router (R13-proven) ---------------------------
// blocks [0,512):      router (32 tokens each) + x->fp16 convert
// blocks [512,1024):   Wk [e][k][n] fp32 -> [e][n][k] fp16 transpose
// blocks [1024,1536):  zero out (16 float4 per thread)
__global__ void __launch_bounds__(256) fused_prep_router(
    const float* __restrict__ x,   const float* __restrict__ eps,
    const float* __restrict__ Wr,  const float* __restrict__ br,
    const float* __restrict__ Wn,  const float* __restrict__ bn,
    const float* __restrict__ Wk,  float* __restrict__ out)
{
    __shared__ union SU {
        float4 w[2][NEXP][DIM / 4];   // 32 KB (router)
        float  s[64][65];             // 16.9 KB (wk transpose)
    } u;
    const int tid = threadIdx.x;

    if (blockIdx.x >= 1024) {                      // ---- zero out ----
        const size_t base = (size_t)(blockIdx.x - 1024) * (256 * 16);
        float4* o4 = (float4*)out;
#pragma unroll
        for (int j = 0; j < 16; j++)
            o4[base + (size_t)j * 256 + tid] = make_float4(0.f, 0.f, 0.f, 0.f);
        return;
    }

    if (blockIdx.x >= 512) {                       // ---- Wk transpose ----
        const int b = blockIdx.x - 512;
        const int e = b >> 6, kt = ((b >> 3) & 7) * 64, nt = (b & 7) * 64;
        const float* src = Wk + ((size_t)e * DIM + kt) * DIM + nt;
#pragma unroll
        for (int j = 0; j < 4; j++) {
            int unit = tid + 256 * j;
            int kr = unit >> 4, nc = (unit & 15) * 4;
            float4 v = *(const float4*)(src + (size_t)kr * DIM + nc);
            u.s[kr][nc + 0] = v.x; u.s[kr][nc + 1] = v.y;
            u.s[kr][nc + 2] = v.z; u.s[kr][nc + 3] = v.w;
        }
        __syncthreads();
        __half* dh = g_wk + ((size_t)e * DIM + nt) * DIM + kt;
#pragma unroll
        for (int j = 0; j < 4; j++) {
            int unit = tid + 256 * j;
            int nr = unit >> 4, kq = (unit & 15) * 4;
            __half2 p0 = __floats2half2_rn(u.s[kq + 0][nr], u.s[kq + 1][nr]);
            __half2 p1 = __floats2half2_rn(u.s[kq + 2][nr], u.s[kq + 3][nr]);
            *(uint2*)(dh + (size_t)nr * DIM + kq) =
                make_uint2(*(uint32_t*)&p0, *(uint32_t*)&p1);
        }
        return;
    }

    // ---- router + x->fp16 (4 tokens/warp, 8 lanes/token; plain fmaf) ----
    {
        float* pr = (float*)u.w[0];
        float* pn = (float*)u.w[1];
        for (int i = tid; i < DIM * NEXP; i += 256) {
            int d = i >> 3, e = i & 7;
            pr[e * DIM + d] = Wr[i];
            pn[e * DIM + d] = Wn[i];
        }
    }
    __syncthreads();

    const int warp = tid >> 5, lane = tid & 31;
    const int grp = lane >> 3, sl = lane & 7;
    const int t = blockIdx.x * 32 + warp * 4 + grp;

    const float4* xr = (const float4*)(x + (size_t)t * DIM);
    float4 xf[16];
#pragma unroll
    for (int i = 0; i < 16; i++) xf[i] = xr[sl + 8 * i];

    {
        uint2* xo = (uint2*)(g_x + (size_t)t * DIM);
#pragma unroll
        for (int i = 0; i < 16; i++) {
            __half2 p0 = __floats2half2_rn(xf[i].x, xf[i].y);
            __half2 p1 = __floats2half2_rn(xf[i].z, xf[i].w);
            xo[sl + 8 * i] = make_uint2(*(uint32_t*)&p0, *(uint32_t*)&p1);
        }
    }

    float noisy[NEXP];
#pragma unroll
    for (int e = 0; e < NEXP; e++) {
        float ar = 0.f, an = 0.f;
#pragma unroll
        for (int i = 0; i < 16; i++) {
            float4 wr = u.w[0][e][sl + 8 * i];
            float4 wn = u.w[1][e][sl + 8 * i];
            ar = fmaf(xf[i].x, wr.x, ar); ar = fmaf(xf[i].y, wr.y, ar);
            ar = fmaf(xf[i].z, wr.z, ar); ar = fmaf(xf[i].w, wr.w, ar);
            an = fmaf(xf[i].x, wn.x, an); an = fmaf(xf[i].y, wn.y, an);
            an = fmaf(xf[i].z, wn.z, an); an = fmaf(xf[i].w, wn.w, an);
        }
#pragma unroll
        for (int o = 4; o; o >>= 1) {
            ar += __shfl_xor_sync(0xffffffffu, ar, o);
            an += __shfl_xor_sync(0xffffffffu, an, o);
        }
        float lg = ar + br[e];
        float nl = an + bn[e];
        float sp = fmaxf(nl, 0.f) + log1pf(expf(-fabsf(nl)));
        noisy[e] = lg + eps[(size_t)t * NEXP + e] * sp;
    }

    if (sl == 0) {
        int i1 = 0; float v1 = noisy[0];
#pragma unroll
        for (int e = 1; e < NEXP; e++) if (noisy[e] > v1) { v1 = noisy[e]; i1 = e; }
        int i2 = -1; float v2 = -INFINITY;
#pragma unroll
        for (int e = 0; e < NEXP; e++) if (e != i1 && noisy[e] > v2) { v2 = noisy[e]; i2 = e; }
        float ex = expf(v2 - v1);
        float inv = 1.f / (1.f + ex);
        int p1 = atomicAdd(&g_count[i1], 1);
        g_tok[i1][p1] = t; g_gate[i1][p1] = inv;
        int p2 = atomicAdd(&g_count[i2], 1);
        g_tok[i2][p2] = t; g_gate[i2][p2] = ex * inv;
    }
}

// ---------------- persistent GEMM: 4 warps, 64x64 warp tiles ----------------
#define ROW_B   144
#define MAT_B   (128 * ROW_B)            // 18432
#define STAGE_B (2 * MAT_B)              // 36864
#define GEMM_SMEM (3 * STAGE_B)          // 110592

__global__ void __launch_bounds__(GTHREADS, 2) expert_gemm_mma(
    const float* __restrict__ bk, float* __restrict__ out)
{
    int off[NEXP + 1];
    off[0] = 0;
#pragma unroll
    for (int e = 0; e < NEXP; e++)
        off[e + 1] = off[e] + ((g_count[e] + BM - 1) >> 7);
    const int total = off[NEXP] * 4;

    extern __shared__ char smem[];
    __shared__ int   sTok [2][BM];
    __shared__ float sGate[2][BM];
    __shared__ int   sNext;

    const int tid = threadIdx.x, wid = tid >> 5, lane = tid & 31;
    const int warp_m = wid & 1, warp_n = wid >> 1;     // 2x2 warps of 64x64
    const uint32_t sb = smem_u32(smem);

    const uint32_t aLd = (uint32_t)((warp_m * 64 + (lane & 15)) * ROW_B + (lane >> 4) * 16);
    const uint32_t bLd = (uint32_t)((warp_n * 64 + ((lane >> 4) * 8) + (lane & 7)) * ROW_B
                                    + ((lane >> 3) & 1) * 16);
    uint32_t stOff[8];
#pragma unroll
    for (int j = 0; j < 8; j++) {
        int unit = tid + GTHREADS * j;                 // 0..1023
        stOff[j] = (uint32_t)((unit >> 3) * ROW_B + (unit & 7) * 16);
    }

    auto decode = [&](int w, int& de, int& dm0, int& dnb, int& dcnt) {
        int rt = w >> 2;
        dnb = (w & 3) << 7;
        int q = 0;
#pragma unroll
        for (int u = 0; u < NEXP - 1; u++) if (rt >= off[u + 1]) q = u + 1;
        de = q;
        dm0 = (rt - off[q]) * BM;
        dcnt = g_count[q];
    };
    // recompute offsets from sTok each stage (8 LDS/thread) to cap regs
    auto issue = [&](int slot, int k0, const int* tokArr, int e_, int nb_) {
        const uint32_t base = sb + slot * STAGE_B;
#pragma unroll
        for (int j = 0; j < 8; j++) {
            int unit = tid + GTHREADS * j;
            int row = unit >> 3, seg = (unit & 7) * 8;
            cp16(base + 0 * MAT_B + stOff[j],
                 g_x + (uint32_t)(tokArr[row] * DIM + seg + k0));
            cp16(base + 1 * MAT_B + stOff[j],
                 g_wk + (uint32_t)(((e_ * DIM) + nb_ + row) * DIM + seg + k0));
        }
        cp_commit();
    };

    if (tid == 0) sNext = atomicAdd(&g_ticket, 1);
    __syncthreads();
    int work = sNext;

    if (work < total) {
        int e, m0, nb, cnt;
        decode(work, e, m0, nb, cnt);
        int p = 0;
        {
            int m = m0 + tid;
            bool v = (m < cnt);
            sTok [p][tid] = v ? g_tok[e][m] : g_tok[e][m0];
            sGate[p][tid] = v ? g_gate[e][m] : 0.f;
        }
        __syncthreads();

        int slotBase = 0;
        issue(0, 0, sTok[p], e, nb);
        issue(1, BK, sTok[p], e, nb);

#pragma unroll 1
        while (true) {
            if (tid == 0) sNext = atomicAdd(&g_ticket, 1);
            __syncthreads();              // publishes sNext; guards sTok[p^1]
            const int nwork = sNext;
            const bool hasNext = (nwork < total);
            int e2 = 0, m02 = 0, nb2 = 0, cnt2 = 0;
            if (hasNext) {
                decode(nwork, e2, m02, nb2, cnt2);
                int m = m02 + tid;
                bool v = (m < cnt2);
                sTok [p ^ 1][tid] = v ? g_tok[e2][m] : g_tok[e2][m02];
                sGate[p ^ 1][tid] = v ? g_gate[e2][m] : 0.f;
            }

            float acc[4][8][4];
#pragma unroll
            for (int i = 0; i < 4; i++)
#pragma unroll
                for (int t = 0; t < 8; t++)
#pragma unroll
                    for (int q = 0; q < 4; q++) acc[i][t][q] = 0.f;

#pragma unroll 1
            for (int st = 0; st < KSTAGES; st++) {
                if (st == KSTAGES - 1 && !hasNext) cp_wait<0>();
                else                               cp_wait<1>();
                __syncthreads();
                if (st + 2 < KSTAGES) {
                    issue((slotBase + st + 2) % 3, (st + 2) * BK, sTok[p], e, nb);
                } else if (hasNext) {
                    const int nst = st + 2 - KSTAGES;     // 0 or 1
                    issue((slotBase + st + 2) % 3, nst * BK, sTok[p ^ 1], e2, nb2);
                }

                const uint32_t base = sb + ((slotBase + st) % 3) * STAGE_B;
                const uint32_t aB = base + 0 * MAT_B + aLd;
                const uint32_t bB = base + 1 * MAT_B + bLd;
#pragma unroll
                for (int kk = 0; kk < 4; kk++) {
                    const uint32_t ko = kk * 32;
                    uint32_t aF[4][4], bF[4][4];
#pragma unroll
                    for (int i = 0; i < 4; i++)
                        ldsm4(aF[i][0], aF[i][1], aF[i][2], aF[i][3],
                              aB + i * 16 * ROW_B + ko);
#pragma unroll
                    for (int q = 0; q < 4; q++)
                        ldsm4(bF[q][0], bF[q][1], bF[q][2], bF[q][3],
                              bB + q * 16 * ROW_B + ko);
#pragma unroll
                    for (int i = 0; i < 4; i++)
#pragma unroll
                        for (int q = 0; q < 4; q++)
#pragma unroll
                            for (int h = 0; h < 2; h++)
                                mma16816(acc[i][2 * q + h], aF[i], &bF[q][h * 2]);
                }
            }

            // epilogue (exactly 2 commutative adds per out element)
            {
                float2 bkf[8];
                const float* bkp = bk + (size_t)e * DIM + nb + warp_n * 64 + (lane & 3) * 2;
#pragma unroll
                for (int t = 0; t < 8; t++) bkf[t] = *(const float2*)(bkp + t * 8);
#pragma unroll
                for (int i = 0; i < 4; i++) {
#pragma unroll
                    for (int half = 0; half < 2; half++) {
                        const int mrow = warp_m * 64 + i * 16 + half * 8 + (lane >> 2);
                        const int m = m0 + mrow;
                        if (m < cnt) {
                            const int   tok = sTok [p][mrow];
                            const float g   = sGate[p][mrow];
                            float* op = out + (size_t)tok * DIM + nb + warp_n * 64 + (lane & 3) * 2;
#pragma unroll
                            for (int t = 0; t < 8; t++)
                                redf2(op + t * 8,
                                      g * (acc[i][t][half * 2 + 0] + bkf[t].x),
                                      g * (acc[i][t][half * 2 + 1] + bkf[t].y));
                        }
                    }
                }
            }

            if (!hasNext) break;
            work = nwork;
            e = e2; m0 = m02; nb = nb2; cnt = cnt2;
            p ^= 1;
            slotBase = (slotBase + KSTAGES) % 3;
        }
    }

    // ---- end-of-kernel state reset (last CTA) ------------------------------
    __syncthreads();
    if (tid == 0) {
        __threadfence();
        int d = atomicAdd(&g_done, 1);
        if (d == GEMM_GRID - 1) {
#pragma unroll
            for (int q = 0; q < NEXP; q++) g_count[q] = 0;
            g_ticket = 0;
            g_done = 0;
        }
    }
}

// ---------------- launch -----------------------------------------------------
extern "C" void kernel_launch(void* const* d_in, const int* in_sizes, int n_in,
                              void* d_out, int out_size) {
    const float* x   = (const float*)d_in[0];
    const float* eps = (const float*)d_in[1];
    const float* Wr  = (const float*)d_in[2];
    const float* br  = (const float*)d_in[3];
    const float* Wn  = (const float*)d_in[4];
    const float* bn  = (const float*)d_in[5];
    const float* Wk  = (const float*)d_in[6];
    const float* bk  = (const float*)d_in[7];
    float* out = (float*)d_out;

    cudaFuncSetAttribute(expert_gemm_mma,
                         cudaFuncAttributeMaxDynamicSharedMemorySize, GEMM_SMEM);

    fused_prep_router<<<1536, 256>>>(x, eps, Wr, br, Wn, bn, Wk, out);
    expert_gemm_mma<<<GEMM_GRID, GTHREADS, GEMM_SMEM>>>(bk, out);
}

// round 17
// speedup vs baseline: 1.0995x; 1.0995x over previous
#include <cuda_runtime.h>
#include <cuda_fp16.h>
#include <math.h>
#include <stdint.h>

#define NTOK  16384
#define DIM   512
#define NEXP  8
#define BM    128
#define BN    128
#define BK    64
#define KSTAGES (DIM / BK)          // 8
#define GEMM_GRID 296               // 2 CTAs x 148 SMs

// ---------------- static device scratch ------------------------------------
__device__ int     g_count[NEXP];
__device__ int     g_ticket;
__device__ int     g_done;
__device__ int     g_tok [NEXP][NTOK];
__device__ float   g_gate[NEXP][NTOK];
__device__ __half  g_x  [NTOK * DIM];
__device__ __half  g_wk [NEXP * DIM * DIM];         // [e][n][k] fp16

// ---------------- helpers ---------------------------------------------------
__device__ __forceinline__ uint32_t smem_u32(const void* p) {
    uint32_t a;
    asm("{ .reg .u64 t; cvta.to.shared.u64 t, %1; cvt.u32.u64 %0, t; }" : "=r"(a) : "l"(p));
    return a;
}
__device__ __forceinline__ void cp16(uint32_t saddr, const void* g) {
    asm volatile("cp.async.cg.shared.global [%0], [%1], 16;" :: "r"(saddr), "l"(g));
}
__device__ __forceinline__ void cp_commit() { asm volatile("cp.async.commit_group;"); }
template<int N> __device__ __forceinline__ void cp_wait() {
    asm volatile("cp.async.wait_group %0;" :: "n"(N));
}
__device__ __forceinline__ void ldsm4(uint32_t& r0, uint32_t& r1, uint32_t& r2, uint32_t& r3,
                                      uint32_t addr) {
    asm volatile("ldmatrix.sync.aligned.m8n8.x4.shared.b16 {%0,%1,%2,%3}, [%4];"
                 : "=r"(r0), "=r"(r1), "=r"(r2), "=r"(r3) : "r"(addr));
}
__device__ __forceinline__ void mma16816(float* c, const uint32_t* a, const uint32_t* b) {
    asm volatile(
        "mma.sync.aligned.m16n8k16.row.col.f32.f16.f16.f32 "
        "{%0,%1,%2,%3}, {%4,%5,%6,%7}, {%8,%9}, {%0,%1,%2,%3};"
        : "+f"(c[0]), "+f"(c[1]), "+f"(c[2]), "+f"(c[3])
        : "r"(a[0]), "r"(a[1]), "r"(a[2]), "r"(a[3]), "r"(b[0]), "r"(b[1]));
}
__device__ __forceinline__ void redf2(float* p, float a, float b) {
    asm volatile("red.global.add.v2.f32 [%0], {%1, %2};"
                 :: "l"(p), "f"(a), "f"(b) : "memory");
}

// ---------------- fused prep + router ---------------------------------------
// blocks [0,256):    router, 64 tokens each; hierarchical count aggregation
// blocks [256,768):  Wk transpose unit + 64KB zero-out of `out`
__global__ void __launch_bounds__(256) fused_prep_router(
    const float* __restrict__ x,   const float* __restrict__ eps,
    const float* __restrict__ Wr,  const float* __restrict__ br,
    const float* __restrict__ Wn,  const float* __restrict__ bn,
    const float* __restrict__ Wk,  float* __restrict__ out)
{
    __shared__ union SU {
        float4 w[2][NEXP][DIM / 4];   // 32 KB (router weights)
        float  s[64][65];             // 16.9 KB (wk transpose)
    } u;
    __shared__ int   sE[2][64];
    __shared__ float sG[2][64];
    __shared__ int   sCnt[NEXP];
    __shared__ int   sBase[NEXP];

    const int tid = threadIdx.x;

    if (blockIdx.x >= 256) {           // ---- Wk transpose + zero-out ----
        const int b = blockIdx.x - 256;
        const int e = b >> 6, kt = ((b >> 3) & 7) * 64, nt = (b & 7) * 64;
        const float* src = Wk + ((size_t)e * DIM + kt) * DIM + nt;
#pragma unroll
        for (int j = 0; j < 4; j++) {
            int unit = tid + 256 * j;
            int kr = unit >> 4, nc = (unit & 15) * 4;
            float4 v = *(const float4*)(src + (size_t)kr * DIM + nc);
            u.s[kr][nc + 0] = v.x; u.s[kr][nc + 1] = v.y;
            u.s[kr][nc + 2] = v.z; u.s[kr][nc + 3] = v.w;
        }
        // overlap the 64KB zero-out with the transpose smem round-trip
        {
            const size_t base = (size_t)b * (256 * 16);
            float4* o4 = (float4*)out;
#pragma unroll
            for (int j = 0; j < 16; j++)
                o4[base + (size_t)j * 256 + tid] = make_float4(0.f, 0.f, 0.f, 0.f);
        }
        __syncthreads();
        __half* dh = g_wk + ((size_t)e * DIM + nt) * DIM + kt;
#pragma unroll
        for (int j = 0; j < 4; j++) {
            int unit = tid + 256 * j;
            int nr = unit >> 4, kq = (unit & 15) * 4;
            __half2 p0 = __floats2half2_rn(u.s[kq + 0][nr], u.s[kq + 1][nr]);
            __half2 p1 = __floats2half2_rn(u.s[kq + 2][nr], u.s[kq + 3][nr]);
            *(uint2*)(dh + (size_t)nr * DIM + kq) =
                make_uint2(*(uint32_t*)&p0, *(uint32_t*)&p1);
        }
        return;
    }

    // ---- router: 64 tokens per block (2 passes of 32) ----
    {
        float* pr = (float*)u.w[0];
        float* pn = (float*)u.w[1];
        for (int i = tid; i < DIM * NEXP; i += 256) {
            int d = i >> 3, e = i & 7;
            pr[e * DIM + d] = Wr[i];
            pn[e * DIM + d] = Wn[i];
        }
        if (tid < NEXP) sCnt[tid] = 0;
    }
    __syncthreads();

    const int warp = tid >> 5, lane = tid & 31;
    const int grp = lane >> 3, sl = lane & 7;

#pragma unroll 1
    for (int pass = 0; pass < 2; pass++) {
        const int li = pass * 32 + warp * 4 + grp;     // local token 0..63
        const int t  = blockIdx.x * 64 + li;

        const float4* xr = (const float4*)(x + (size_t)t * DIM);
        float4 xf[16];
#pragma unroll
        for (int i = 0; i < 16; i++) xf[i] = xr[sl + 8 * i];

        {
            uint2* xo = (uint2*)(g_x + (size_t)t * DIM);
#pragma unroll
            for (int i = 0; i < 16; i++) {
                __half2 p0 = __floats2half2_rn(xf[i].x, xf[i].y);
                __half2 p1 = __floats2half2_rn(xf[i].z, xf[i].w);
                xo[sl + 8 * i] = make_uint2(*(uint32_t*)&p0, *(uint32_t*)&p1);
            }
        }

        float noisy[NEXP];
#pragma unroll
        for (int e = 0; e < NEXP; e++) {
            float ar = 0.f, an = 0.f;
#pragma unroll
            for (int i = 0; i < 16; i++) {
                float4 wr = u.w[0][e][sl + 8 * i];
                float4 wn = u.w[1][e][sl + 8 * i];
                ar = fmaf(xf[i].x, wr.x, ar); ar = fmaf(xf[i].y, wr.y, ar);
                ar = fmaf(xf[i].z, wr.z, ar); ar = fmaf(xf[i].w, wr.w, ar);
                an = fmaf(xf[i].x, wn.x, an); an = fmaf(xf[i].y, wn.y, an);
                an = fmaf(xf[i].z, wn.z, an); an = fmaf(xf[i].w, wn.w, an);
            }
#pragma unroll
            for (int o = 4; o; o >>= 1) {
                ar += __shfl_xor_sync(0xffffffffu, ar, o);
                an += __shfl_xor_sync(0xffffffffu, an, o);
            }
            float lg = ar + br[e];
            float nl = an + bn[e];
            float sp = fmaxf(nl, 0.f) + log1pf(expf(-fabsf(nl)));
            noisy[e] = lg + eps[(size_t)t * NEXP + e] * sp;
        }

        if (sl == 0) {
            int i1 = 0; float v1 = noisy[0];
#pragma unroll
            for (int e = 1; e < NEXP; e++) if (noisy[e] > v1) { v1 = noisy[e]; i1 = e; }
            int i2 = -1; float v2 = -INFINITY;
#pragma unroll
            for (int e = 0; e < NEXP; e++)
                if (e != i1 && noisy[e] > v2) { v2 = noisy[e]; i2 = e; }
            float ex = expf(v2 - v1);
            float inv = 1.f / (1.f + ex);
            sE[0][li] = i1; sG[0][li] = inv;
            sE[1][li] = i2; sG[1][li] = ex * inv;
        }
    }
    __syncthreads();

    // hierarchical scatter: 128 assignments -> smem offsets -> 8 global atomics
    int myE = 0, myOff = 0;
    float myG = 0.f;
    if (tid < 128) {
        const int li = tid >> 1, which = tid & 1;
        myE = sE[which][li];
        myG = sG[which][li];
        myOff = atomicAdd(&sCnt[myE], 1);
    }
    __syncthreads();
    if (tid < NEXP) sBase[tid] = atomicAdd(&g_count[tid], sCnt[tid]);
    __syncthreads();
    if (tid < 128) {
        const int pos = sBase[myE] + myOff;
        g_tok [myE][pos] = blockIdx.x * 64 + (tid >> 1);
        g_gate[myE][pos] = myG;
    }
}

// ---------------- persistent GEMM (R13-proven, 71.7us) ----------------------
#define ROW_B   144
#define MAT_B   (128 * ROW_B)            // 18432
#define STAGE_B (2 * MAT_B)              // 36864
#define GEMM_SMEM (3 * STAGE_B)          // 110592

__global__ void __launch_bounds__(256, 2) expert_gemm_mma(
    const float* __restrict__ bk, float* __restrict__ out)
{
    int off[NEXP + 1];
    off[0] = 0;
#pragma unroll
    for (int e = 0; e < NEXP; e++)
        off[e + 1] = off[e] + ((g_count[e] + BM - 1) >> 7);
    const int total = off[NEXP] * 4;

    extern __shared__ char smem[];
    __shared__ int   sTok [2][BM];
    __shared__ float sGate[2][BM];
    __shared__ int   sNext;

    const int tid = threadIdx.x, wid = tid >> 5, lane = tid & 31;
    const int warp_m = wid & 3, warp_n = wid >> 2;
    const uint32_t sb = smem_u32(smem);

    const uint32_t aLd = (uint32_t)((warp_m * 32 + (lane & 15)) * ROW_B + (lane >> 4) * 16);
    const uint32_t bLd = (uint32_t)((warp_n * 64 + ((lane >> 4) * 8) + (lane & 7)) * ROW_B
                                    + ((lane >> 3) & 1) * 16);
    uint32_t stOff[4];
#pragma unroll
    for (int j = 0; j < 4; j++) {
        int unit = tid + 256 * j;
        stOff[j] = (uint32_t)((unit >> 3) * ROW_B + (unit & 7) * 16);
    }

    auto decode = [&](int w, int& de, int& dm0, int& dnb, int& dcnt) {
        int rt = w >> 2;
        dnb = (w & 3) << 7;
        int q = 0;
#pragma unroll
        for (int u = 0; u < NEXP - 1; u++) if (rt >= off[u + 1]) q = u + 1;
        de = q;
        dm0 = (rt - off[q]) * BM;
        dcnt = g_count[q];
    };
    auto calc_offs = [&](int e_, int nb_, const int* tokArr, uint32_t* aO, uint32_t* bO) {
#pragma unroll
        for (int j = 0; j < 4; j++) {
            int unit = tid + 256 * j;
            int row = unit >> 3, seg = unit & 7;
            aO[j] = (uint32_t)(tokArr[row] * DIM + seg * 8);
            bO[j] = (uint32_t)(((e_ * DIM) + nb_ + row) * DIM + seg * 8);
        }
    };
    auto issue = [&](int slot, int k0, const uint32_t* aO, const uint32_t* bO) {
        const uint32_t base = sb + slot * STAGE_B;
#pragma unroll
        for (int j = 0; j < 4; j++) {
            cp16(base + 0 * MAT_B + stOff[j], g_x  + aO[j] + k0);
            cp16(base + 1 * MAT_B + stOff[j], g_wk + bO[j] + k0);
        }
        cp_commit();
    };

    if (tid == 0) sNext = atomicAdd(&g_ticket, 1);
    __syncthreads();
    int work = sNext;

    if (work < total) {
        int e, m0, nb, cnt;
        decode(work, e, m0, nb, cnt);
        int p = 0;
        if (tid < BM) {
            int m = m0 + tid;
            bool v = (m < cnt);
            sTok [p][tid] = v ? g_tok[e][m] : g_tok[e][m0];
            sGate[p][tid] = v ? g_gate[e][m] : 0.f;
        }
        __syncthreads();

        uint32_t aOff[4], bOff[4];
        calc_offs(e, nb, sTok[p], aOff, bOff);
        int slotBase = 0;
        issue(0, 0, aOff, bOff);
        issue(1, BK, aOff, bOff);

#pragma unroll 1
        while (true) {
            if (tid == 0) sNext = atomicAdd(&g_ticket, 1);
            __syncthreads();
            const int nwork = sNext;
            const bool hasNext = (nwork < total);
            int e2 = 0, m02 = 0, nb2 = 0, cnt2 = 0;
            if (hasNext) {
                decode(nwork, e2, m02, nb2, cnt2);
                if (tid < BM) {
                    int m = m02 + tid;
                    bool v = (m < cnt2);
                    sTok [p ^ 1][tid] = v ? g_tok[e2][m] : g_tok[e2][m02];
                    sGate[p ^ 1][tid] = v ? g_gate[e2][m] : 0.f;
                }
            }

            float acc[2][8][4];
#pragma unroll
            for (int i = 0; i < 2; i++)
#pragma unroll
                for (int t = 0; t < 8; t++)
#pragma unroll
                    for (int q = 0; q < 4; q++) acc[i][t][q] = 0.f;

            uint32_t aOff2[4], bOff2[4];

#pragma unroll 1
            for (int st = 0; st < KSTAGES; st++) {
                if (st == KSTAGES - 1 && !hasNext) cp_wait<0>();
                else                               cp_wait<1>();
                __syncthreads();
                if (st + 2 < KSTAGES) {
                    issue((slotBase + st + 2) % 3, (st + 2) * BK, aOff, bOff);
                } else if (hasNext) {
                    const int nst = st + 2 - KSTAGES;
                    if (nst == 0) calc_offs(e2, nb2, sTok[p ^ 1], aOff2, bOff2);
                    issue((slotBase + st + 2) % 3, nst * BK, aOff2, bOff2);
                }

                const uint32_t base = sb + ((slotBase + st) % 3) * STAGE_B;
                const uint32_t aB = base + 0 * MAT_B + aLd;
                const uint32_t bB = base + 1 * MAT_B + bLd;
#pragma unroll
                for (int kk = 0; kk < 4; kk++) {
                    const uint32_t ko = kk * 32;
                    uint32_t aF[2][4], bF[4][4];
#pragma unroll
                    for (int i = 0; i < 2; i++)
                        ldsm4(aF[i][0], aF[i][1], aF[i][2], aF[i][3], aB + i * 16 * ROW_B + ko);
#pragma unroll
                    for (int q = 0; q < 4; q++)
                        ldsm4(bF[q][0], bF[q][1], bF[q][2], bF[q][3], bB + q * 16 * ROW_B + ko);
#pragma unroll
                    for (int i = 0; i < 2; i++)
#pragma unroll
                        for (int q = 0; q < 4; q++)
#pragma unroll
                            for (int h = 0; h < 2; h++)
                                mma16816(acc[i][2 * q + h], aF[i], &bF[q][h * 2]);
                }
            }

            // epilogue (exactly 2 commutative adds per out element)
            {
                float2 bkf[8];
                const float* bkp = bk + (size_t)e * DIM + nb + warp_n * 64 + (lane & 3) * 2;
#pragma unroll
                for (int t = 0; t < 8; t++) bkf[t] = *(const float2*)(bkp + t * 8);
#pragma unroll
                for (int i = 0; i < 2; i++) {
#pragma unroll
                    for (int half = 0; half < 2; half++) {
                        const int mrow = warp_m * 32 + i * 16 + half * 8 + (lane >> 2);
                        const int m = m0 + mrow;
                        if (m < cnt) {
                            const int   tok = sTok [p][mrow];
                            const float g   = sGate[p][mrow];
                            float* op = out + (size_t)tok * DIM + nb + warp_n * 64 + (lane & 3) * 2;
#pragma unroll
                            for (int t = 0; t < 8; t++)
                                redf2(op + t * 8,
                                      g * (acc[i][t][half * 2 + 0] + bkf[t].x),
                                      g * (acc[i][t][half * 2 + 1] + bkf[t].y));
                        }
                    }
                }
            }

            if (!hasNext) break;
            work = nwork;
            e = e2; m0 = m02; nb = nb2; cnt = cnt2;
#pragma unroll
            for (int j = 0; j < 4; j++) { aOff[j] = aOff2[j]; bOff[j] = bOff2[j]; }
            p ^= 1;
            slotBase = (slotBase + KSTAGES) % 3;
        }
    }

    // ---- end-of-kernel state reset (last CTA) ------------------------------
    __syncthreads();
    if (tid == 0) {
        __threadfence();
        int d = atomicAdd(&g_done, 1);
        if (d == GEMM_GRID - 1) {
#pragma unroll
            for (int q = 0; q < NEXP; q++) g_count[q] = 0;
            g_ticket = 0;
            g_done = 0;
        }
    }
}

// ---------------- launch -----------------------------------------------------
extern "C" void kernel_launch(void* const* d_in, const int* in_sizes, int n_in,
                              void* d_out, int out_size) {
    const float* x   = (const float*)d_in[0];
    const float* eps = (const float*)d_in[1];
    const float* Wr  = (const float*)d_in[2];
    const float* br  = (const float*)d_in[3];
    const float* Wn  = (const float*)d_in[4];
    const float* bn  = (const float*)d_in[5];
    const float* Wk  = (const float*)d_in[6];
    const float* bk  = (const float*)d_in[7];
    float* out = (float*)d_out;

    cudaFuncSetAttribute(expert_gemm_mma,
                         cudaFuncAttributeMaxDynamicSharedMemorySize, GEMM_SMEM);

    fused_prep_router<<<768, 256>>>(x, eps, Wr, br, Wn, bn, Wk, out);
    expert_gemm_mma<<<GEMM_GRID, 256, GEMM_SMEM>>>(bk, out);
}